// round 16
// baseline (speedup 1.0000x reference)
#include <cuda_runtime.h>
#include <cuda_fp16.h>
#include <cstdint>
#include <cstddef>

#define BN_ 4
#define TN_ 2048
#define SN_ 2048
#define EN_ 512
#define HN_ 8
#define DH_ 64
#define MPROJ (BN_ * TN_)
#define NSB 4
#define NSBLK (SN_ / (128 * NSB))          // 4
#define NSPLIT 4
#define SCHUNK (SN_ / NSPLIT)              // 512
#define OUT0_ELEMS ((size_t)BN_ * TN_ * EN_)
#define P_ELEMS    ((size_t)BN_ * HN_ * TN_ * SN_)
#define CTX_ELEMS  ((size_t)MPROJ * EN_)
#define CM_WORDS   (SN_ / 32)
#define EH_ (EN_ / 2)
#define DHH_ (DH_ / 2)
#define SNH_ (SN_ / 2)

__device__ uint32_t g_Q[(size_t)MPROJ * EH_];
__device__ uint32_t g_K[(size_t)MPROJ * EH_];
__device__ uint32_t g_V[(size_t)MPROJ * EH_];
__device__ uint32_t g_EH[(size_t)BN_ * HN_ * TN_ * SNH_];
__device__ float g_CTX[CTX_ELEMS];
__device__ float g_CTXP[(size_t)NSPLIT * CTX_ELEMS];
__device__ float g_PART[(size_t)BN_ * HN_ * TN_ * NSBLK];
__device__ uint32_t g_CMASK[(size_t)BN_ * TN_ * CM_WORDS];

__device__ __forceinline__ uint32_t pack_half2(float lo, float hi) {
    __half2 h = __floats2half2_rn(lo, hi);
    return *(uint32_t*)&h;
}
__device__ __forceinline__ float2 unpack_half2(uint32_t u) {
    return __half22float2(*(__half2*)&u);
}
__device__ __forceinline__ uint32_t ex2_f16x2(uint32_t x) {
    uint32_t r;
    asm("ex2.approx.f16x2 %0, %1;" : "=r"(r) : "r"(x));
    return r;
}

__device__ __forceinline__ void mma_f16(
    float& d0, float& d1, float& d2, float& d3,
    uint32_t a0, uint32_t a1, uint32_t a2, uint32_t a3,
    uint32_t b0, uint32_t b1)
{
    asm volatile(
        "mma.sync.aligned.m16n8k16.row.col.f32.f16.f16.f32 "
        "{%0,%1,%2,%3}, {%4,%5,%6,%7}, {%8,%9}, {%0,%1,%2,%3};"
        : "+f"(d0), "+f"(d1), "+f"(d2), "+f"(d3)
        : "r"(a0), "r"(a1), "r"(a2), "r"(a3), "r"(b0), "r"(b1));
}

__device__ __forceinline__ void cp_async16(uint32_t smem_addr, const void* gptr) {
    asm volatile("cp.async.cg.shared.global [%0], [%1], 16;"
                 :: "r"(smem_addr), "l"(gptr));
}
#define CP_COMMIT() asm volatile("cp.async.commit_group;")
#define CP_WAIT0()  asm volatile("cp.async.wait_group 0;")

// ---------------------------------------------------------------------------
__global__ __launch_bounds__(256) void pack_mask_kernel(
    const unsigned char* __restrict__ attn_mask,
    const unsigned char* __restrict__ kpm,
    uint32_t* __restrict__ cmask)
{
    size_t idx = (size_t)blockIdx.x * 256 + threadIdx.x;
    int w = (int)(idx & (CM_WORDS - 1));
    size_t bt = idx >> 6;
    int t = (int)(bt & (TN_ - 1));
    int b = (int)(bt >> 11);

    const uint32_t* am = (const uint32_t*)&attn_mask[(size_t)t * SN_ + w * 32];
    const uint32_t* kp = (const uint32_t*)&kpm[(size_t)b * SN_ + w * 32];
    uint32_t bits = 0;
#pragma unroll
    for (int j = 0; j < 8; j++) {
        uint32_t u = am[j] | kp[j];
#pragma unroll
        for (int k = 0; k < 4; k++)
            if ((u >> (8 * k)) & 255u) bits |= 1u << (4 * j + k);
    }
    cmask[idx] = bits;
}

// ---------------------------------------------------------------------------
// Kernel A: fp16 scores in log2 domain, persistent over 4 s-tiles,
// cp.async double-buffered K, mask + ex2.f16x2 + half2 E write.
// ---------------------------------------------------------------------------
__global__ __launch_bounds__(256, 2) void scores_exp_kernel(
    const uint32_t* __restrict__ Q, const uint32_t* __restrict__ Kp,
    const uint32_t* __restrict__ cmask,
    uint32_t* __restrict__ EH, float* __restrict__ part)
{
    extern __shared__ uint32_t smem_u[];
    uint32_t* Qs  = smem_u;
    uint32_t* Ks0 = smem_u + 128 * 36;
    uint32_t* Ks1 = smem_u + 2 * 128 * 36;
    __shared__ float ssum[4][128];

    int bh = blockIdx.z;
    int b = bh >> 3;
    int h = bh & 7;
    int t0 = blockIdx.y * 128;
    int sBase = blockIdx.x * (128 * NSB);
    int tid = threadIdx.x;
    int warp = tid >> 5, lane = tid & 31;
    int g = lane >> 2, t = lane & 3;
    int wm = (warp >> 2) * 64;
    int wn = (warp & 3) * 32;

    const uint32_t* Qb = Q + (size_t)b * TN_ * EH_ + (size_t)h * DHH_;
    const uint32_t* Kb = Kp + (size_t)b * SN_ * EH_ + (size_t)h * DHH_;

    uint32_t qs_a  = (uint32_t)__cvta_generic_to_shared(Qs);
    uint32_t ks_a[2] = { (uint32_t)__cvta_generic_to_shared(Ks0),
                         (uint32_t)__cvta_generic_to_shared(Ks1) };

#pragma unroll
    for (int i = 0; i < 4; i++) {
        int f = tid + i * 256;
        int r = f >> 3;
        int ch = (f & 7) * 4;
        cp_async16(qs_a + (r * 36 + ch) * 4, Qb + (size_t)(t0 + r) * EH_ + ch);
    }
#pragma unroll
    for (int i = 0; i < 4; i++) {
        int f = tid + i * 256;
        int r = f >> 3;
        int ch = (f & 7) * 4;
        cp_async16(ks_a[0] + (r * 36 + ch) * 4, Kb + (size_t)(sBase + r) * EH_ + ch);
    }
    CP_COMMIT();

    uint32_t* Eb = EH + (size_t)bh * TN_ * SNH_;
    const uint32_t* cm = cmask + ((size_t)b * TN_ << 6);
    float partial[4][2] = {};

    CP_WAIT0();
    __syncthreads();

    for (int si = 0; si < NSB; si++) {
        uint32_t* Kcur = (si & 1) ? Ks1 : Ks0;

        if (si + 1 < NSB) {
            int s0n = sBase + (si + 1) * 128;
            uint32_t dst = ks_a[(si + 1) & 1];
#pragma unroll
            for (int i = 0; i < 4; i++) {
                int f = tid + i * 256;
                int r = f >> 3;
                int ch = (f & 7) * 4;
                cp_async16(dst + (r * 36 + ch) * 4, Kb + (size_t)(s0n + r) * EH_ + ch);
            }
            CP_COMMIT();
        }

        int s0 = sBase + si * 128;

        float acc[4][4][4] = {};
#pragma unroll
        for (int kk2 = 0; kk2 < 32; kk2 += 8) {
            uint32_t a[4][4];
#pragma unroll
            for (int i = 0; i < 4; i++) {
                int base = (wm + 16 * i + g) * 36 + kk2 + t;
                a[i][0] = Qs[base];
                a[i][1] = Qs[base + 8 * 36];
                a[i][2] = Qs[base + 4];
                a[i][3] = Qs[base + 8 * 36 + 4];
            }
            uint32_t bf[4][2];
#pragma unroll
            for (int j = 0; j < 4; j++) {
                int base = (wn + 8 * j + g) * 36 + kk2 + t;
                bf[j][0] = Kcur[base];
                bf[j][1] = Kcur[base + 4];
            }
#pragma unroll
            for (int i = 0; i < 4; i++)
#pragma unroll
                for (int j = 0; j < 4; j++)
                    mma_f16(acc[i][j][0], acc[i][j][1], acc[i][j][2], acc[i][j][3],
                            a[i][0], a[i][1], a[i][2], a[i][3], bf[j][0], bf[j][1]);
        }

        int w = (s0 + wn) >> 5;
#pragma unroll
        for (int i = 0; i < 4; i++) {
            int tg0 = t0 + wm + 16 * i + g;
            int tg1 = tg0 + 8;
            uint32_t w0 = cm[((size_t)tg0 << 6) + w];
            uint32_t w1 = cm[((size_t)tg1 << 6) + w];
#pragma unroll
            for (int j = 0; j < 4; j++) {
                int bit = 8 * j + 2 * t;
                int sh = (s0 + wn + bit) >> 1;
                float m00 = ((w0 >> bit) & 1u) ? -100.f : acc[i][j][0];
                float m01 = ((w0 >> bit) & 2u) ? -100.f : acc[i][j][1];
                float m10 = ((w1 >> bit) & 1u) ? -100.f : acc[i][j][2];
                float m11 = ((w1 >> bit) & 2u) ? -100.f : acc[i][j][3];
                uint32_t p0 = ex2_f16x2(pack_half2(m00, m01));
                uint32_t p1 = ex2_f16x2(pack_half2(m10, m11));
                __stcs(&Eb[(size_t)tg0 * SNH_ + sh], p0);
                __stcs(&Eb[(size_t)tg1 * SNH_ + sh], p1);
                float2 f0 = unpack_half2(p0);
                float2 f1 = unpack_half2(p1);
                partial[i][0] += f0.x + f0.y;
                partial[i][1] += f1.x + f1.y;
            }
        }

        if (si + 1 < NSB) {
            CP_WAIT0();
            __syncthreads();
        }
    }

#pragma unroll
    for (int i = 0; i < 4; i++)
#pragma unroll
        for (int hh = 0; hh < 2; hh++) {
            float v = partial[i][hh];
            v += __shfl_xor_sync(0xFFFFFFFFu, v, 1);
            v += __shfl_xor_sync(0xFFFFFFFFu, v, 2);
            partial[i][hh] = v;
        }
    if (t == 0) {
#pragma unroll
        for (int i = 0; i < 4; i++)
#pragma unroll
            for (int hh = 0; hh < 2; hh++)
                ssum[warp & 3][wm + 16 * i + 8 * hh + g] = partial[i][hh];
    }
    __syncthreads();
    if (tid < 128) {
        float l = ssum[0][tid] + ssum[1][tid] + ssum[2][tid] + ssum[3][tid];
        part[((size_t)bh * TN_ + t0 + tid) * NSBLK + blockIdx.x] = l;
    }
}

// ---------------------------------------------------------------------------
// Kernel B (R14 form + 3 blocks/SM): split-S PV (fp16 mma), packed-half2 E,
// fused invl, register prefetch, single smem buffer (2 syncs/iter).
// ---------------------------------------------------------------------------
__global__ __launch_bounds__(256, 3) void pv_norm_kernel(
    float* __restrict__ P, const uint32_t* __restrict__ EH,
    const uint32_t* __restrict__ V,
    const float* __restrict__ part, float* __restrict__ ctxp, int writeP)
{
    extern __shared__ uint32_t smem_b[];
    uint32_t* Ps = smem_b;                 // 128 * 36
    uint32_t* Vs = smem_b + 128 * 36;      // 32 * 72
    float* sinv = (float*)(smem_b + 128 * 36 + 32 * 72);

    int bh = blockIdx.z;
    int b = bh >> 3;
    int h = bh & 7;
    int sc = blockIdx.y;
    int t0 = blockIdx.x * 128;
    int tid = threadIdx.x;
    int warp = tid >> 5, lane = tid & 31;
    int g = lane >> 2, t = lane & 3;
    int wm = (warp >> 1) * 32;
    int wn = (warp & 1) * 32;

    float* Pb = P + ((size_t)bh * TN_ + t0) * SN_;
    const uint32_t* Eb = EH + ((size_t)bh * TN_ + t0) * SNH_;
    const uint32_t* Vb = V + (size_t)b * SN_ * EH_ + (size_t)h * DHH_;

    if (tid < 128) {
        float4 v = *(const float4*)&part[((size_t)bh * TN_ + t0 + tid) * NSBLK];
        sinv[tid] = 1.0f / ((v.x + v.y) + (v.z + v.w));
    }

    uint4 eReg[4];
    uint4 vReg[2];

    {
        int k0h = sc * (SCHUNK / 2);
#pragma unroll
        for (int i = 0; i < 4; i++) {
            int f = tid + i * 256;
            int r = f >> 3, c = (f & 7) * 4;
            eReg[i] = __ldcs((const uint4*)&Eb[(size_t)r * SNH_ + k0h + c]);
        }
#pragma unroll
        for (int i = 0; i < 2; i++) {
            int f = tid + i * 256;
            int sp = f >> 4, cg = f & 15;
            const uint32_t* r0 = Vb + (size_t)(sc * SCHUNK + 2 * sp) * EH_ + 2 * cg;
            uint2 v0 = *(const uint2*)r0;
            uint2 v1 = *(const uint2*)(r0 + EH_);
            vReg[i] = make_uint4(v0.x, v0.y, v1.x, v1.y);
        }
    }
    __syncthreads();

    float acc[2][4][4] = {};
    const int NIT = SCHUNK / 64;   // 8

    for (int it = 0; it < NIT; it++) {
        int k0 = sc * SCHUNK + it * 64;
#pragma unroll
        for (int i = 0; i < 4; i++) {
            int f = tid + i * 256;
            int r = f >> 3, c = (f & 7) * 4;
            uint4 e = eReg[i];
            *(uint4*)&Ps[r * 36 + c] = e;
            if (writeP) {
                float iv = sinv[r];
                float2 f0 = unpack_half2(e.x);
                float2 f1 = unpack_half2(e.y);
                float2 f2 = unpack_half2(e.z);
                float2 f3 = unpack_half2(e.w);
                float4 o0 = make_float4(f0.x * iv, f0.y * iv, f1.x * iv, f1.y * iv);
                float4 o1 = make_float4(f2.x * iv, f2.y * iv, f3.x * iv, f3.y * iv);
                __stcs((float4*)&Pb[(size_t)r * SN_ + k0 + 2 * c], o0);
                __stcs((float4*)&Pb[(size_t)r * SN_ + k0 + 2 * c + 4], o1);
            }
        }
#pragma unroll
        for (int i = 0; i < 2; i++) {
            int f = tid + i * 256;
            int sp = f >> 4, cg = f & 15;
            __half2 a0 = *(__half2*)&vReg[i].x;
            __half2 a1 = *(__half2*)&vReg[i].y;
            __half2 b0 = *(__half2*)&vReg[i].z;
            __half2 b1 = *(__half2*)&vReg[i].w;
            __half2 o0 = __lows2half2(a0, b0);
            __half2 o1 = __highs2half2(a0, b0);
            __half2 o2 = __lows2half2(a1, b1);
            __half2 o3 = __highs2half2(a1, b1);
            uint32_t* dst = &Vs[sp * 72 + 4 * cg];
            dst[0] = *(uint32_t*)&o0; dst[1] = *(uint32_t*)&o1;
            dst[2] = *(uint32_t*)&o2; dst[3] = *(uint32_t*)&o3;
        }
        __syncthreads();

        if (it + 1 < NIT) {
            int k1 = k0 + 64;
            int k1h = k1 >> 1;
#pragma unroll
            for (int i = 0; i < 4; i++) {
                int f = tid + i * 256;
                int r = f >> 3, c = (f & 7) * 4;
                eReg[i] = __ldcs((const uint4*)&Eb[(size_t)r * SNH_ + k1h + c]);
            }
#pragma unroll
            for (int i = 0; i < 2; i++) {
                int f = tid + i * 256;
                int sp = f >> 4, cg = f & 15;
                const uint32_t* r0 = Vb + (size_t)(k1 + 2 * sp) * EH_ + 2 * cg;
                uint2 v0 = *(const uint2*)r0;
                uint2 v1 = *(const uint2*)(r0 + EH_);
                vReg[i] = make_uint4(v0.x, v0.y, v1.x, v1.y);
            }
        }

#pragma unroll
        for (int kk2 = 0; kk2 < 32; kk2 += 8) {
            uint32_t a[2][4];
#pragma unroll
            for (int i = 0; i < 2; i++) {
                int base = (wm + 16 * i + g) * 36 + kk2 + t;
                a[i][0] = Ps[base];
                a[i][1] = Ps[base + 8 * 36];
                a[i][2] = Ps[base + 4];
                a[i][3] = Ps[base + 8 * 36 + 4];
            }
            uint32_t bf[4][2];
#pragma unroll
            for (int j = 0; j < 4; j++) {
                int col = wn + 8 * j + g;
                bf[j][0] = Vs[(kk2 + t) * 72 + col];
                bf[j][1] = Vs[(kk2 + t + 4) * 72 + col];
            }
#pragma unroll
            for (int i = 0; i < 2; i++)
#pragma unroll
                for (int j = 0; j < 4; j++)
                    mma_f16(acc[i][j][0], acc[i][j][1], acc[i][j][2], acc[i][j][3],
                            a[i][0], a[i][1], a[i][2], a[i][3], bf[j][0], bf[j][1]);
        }
        __syncthreads();
    }

    float* Cp = ctxp + (size_t)sc * CTX_ELEMS + (size_t)b * TN_ * EN_ + (size_t)h * DH_;
#pragma unroll
    for (int i = 0; i < 2; i++) {
        int rl0 = wm + 16 * i + g;
        int rl1 = rl0 + 8;
        float iv0 = sinv[rl0];
        float iv1 = sinv[rl1];
        int r0 = t0 + rl0, r1 = t0 + rl1;
#pragma unroll
        for (int j = 0; j < 4; j++) {
            int d = wn + 8 * j + 2 * t;
            *(float2*)&Cp[(size_t)r0 * EN_ + d] =
                make_float2(acc[i][j][0] * iv0, acc[i][j][1] * iv0);
            *(float2*)&Cp[(size_t)r1 * EN_ + d] =
                make_float2(acc[i][j][2] * iv1, acc[i][j][3] * iv1);
        }
    }
}

// ---------------------------------------------------------------------------
__global__ __launch_bounds__(256) void combine_ctx_kernel(
    const float* __restrict__ ctxp, float* __restrict__ ctx)
{
    size_t i = ((size_t)blockIdx.x * 256 + threadIdx.x) * 4;
    float4 a = __ldcs((const float4*)&ctxp[0 * CTX_ELEMS + i]);
    float4 b = __ldcs((const float4*)&ctxp[1 * CTX_ELEMS + i]);
    float4 c = __ldcs((const float4*)&ctxp[2 * CTX_ELEMS + i]);
    float4 d = __ldcs((const float4*)&ctxp[3 * CTX_ELEMS + i]);
    float4 o;
    o.x = (a.x + b.x) + (c.x + d.x);
    o.y = (a.y + b.y) + (c.y + d.y);
    o.z = (a.z + b.z) + (c.z + d.z);
    o.w = (a.w + b.w) + (c.w + d.w);
    *(float4*)&ctx[i] = o;
}

// ---------------------------------------------------------------------------
// Projection GEMM, fp16 mma (fp32 accum), register prefetch, BK=32.
// ---------------------------------------------------------------------------
struct ProjArgs {
    const float* A[3];
    const float* W[3];
    const float* bias[3];
    void* C[3];
    float scale[3];
    int cvt[3];
};

__global__ __launch_bounds__(256) void gemm_bias_kernel(
    ProjArgs args, int K)
{
    __shared__ uint32_t As[128 * 20];
    __shared__ uint32_t Ws[16 * 136];

    int z = blockIdx.z;
    const float* __restrict__ A = args.A[z];
    const float* __restrict__ W = args.W[z];
    const float* __restrict__ bias = args.bias[z];
    float scale = args.scale[z];
    int cvt = args.cvt[z];
    const int N = EN_;

    int tid = threadIdx.x;
    int warp = tid >> 5, lane = tid & 31;
    int g = lane >> 2, t = lane & 3;
    int wm = (warp >> 2) * 64;
    int wn = (warp & 3) * 32;
    int bm = blockIdx.y * 128, bn = blockIdx.x * 128;

    float acc[4][4][4] = {};

    float4 aReg[4];
    float4 wReg[2][2];
#pragma unroll
    for (int i = 0; i < 4; i++) {
        int f = tid + i * 256;
        int r = f >> 3, c = (f & 7) * 4;
        aReg[i] = *(const float4*)&A[(size_t)(bm + r) * K + c];
    }
#pragma unroll
    for (int i = 0; i < 2; i++) {
        int f = tid + i * 256;
        int kp = f >> 5, ng = (f & 31) * 4;
        wReg[i][0] = *(const float4*)&W[(size_t)(2 * kp) * N + bn + ng];
        wReg[i][1] = *(const float4*)&W[(size_t)(2 * kp + 1) * N + bn + ng];
    }

    for (int k0 = 0; k0 < K; k0 += 32) {
#pragma unroll
        for (int i = 0; i < 4; i++) {
            int f = tid + i * 256;
            int r = f >> 3, c = (f & 7) * 4;
            float4 v = aReg[i];
            As[r * 20 + (c >> 1)]     = pack_half2(v.x, v.y);
            As[r * 20 + (c >> 1) + 1] = pack_half2(v.z, v.w);
        }
#pragma unroll
        for (int i = 0; i < 2; i++) {
            int f = tid + i * 256;
            int kp = f >> 5, ng = (f & 31) * 4;
            float4 lo = wReg[i][0], hi = wReg[i][1];
            uint32_t* dst = &Ws[kp * 136 + ng];
            dst[0] = pack_half2(lo.x, hi.x);
            dst[1] = pack_half2(lo.y, hi.y);
            dst[2] = pack_half2(lo.z, hi.z);
            dst[3] = pack_half2(lo.w, hi.w);
        }
        __syncthreads();

        if (k0 + 32 < K) {
            int k1 = k0 + 32;
#pragma unroll
            for (int i = 0; i < 4; i++) {
                int f = tid + i * 256;
                int r = f >> 3, c = (f & 7) * 4;
                aReg[i] = *(const float4*)&A[(size_t)(bm + r) * K + k1 + c];
            }
#pragma unroll
            for (int i = 0; i < 2; i++) {
                int f = tid + i * 256;
                int kp = f >> 5, ng = (f & 31) * 4;
                wReg[i][0] = *(const float4*)&W[(size_t)(k1 + 2 * kp) * N + bn + ng];
                wReg[i][1] = *(const float4*)&W[(size_t)(k1 + 2 * kp + 1) * N + bn + ng];
            }
        }

#pragma unroll
        for (int kk2 = 0; kk2 < 16; kk2 += 8) {
            uint32_t a[4][4];
#pragma unroll
            for (int i = 0; i < 4; i++) {
                int base = (wm + 16 * i + g) * 20 + kk2 + t;
                a[i][0] = As[base];
                a[i][1] = As[base + 8 * 20];
                a[i][2] = As[base + 4];
                a[i][3] = As[base + 8 * 20 + 4];
            }
            uint32_t bf[4][2];
#pragma unroll
            for (int j = 0; j < 4; j++) {
                int col = wn + 8 * j + g;
                bf[j][0] = Ws[(kk2 + t) * 136 + col];
                bf[j][1] = Ws[(kk2 + t + 4) * 136 + col];
            }
#pragma unroll
            for (int i = 0; i < 4; i++)
#pragma unroll
                for (int j = 0; j < 4; j++)
                    mma_f16(acc[i][j][0], acc[i][j][1], acc[i][j][2], acc[i][j][3],
                            a[i][0], a[i][1], a[i][2], a[i][3], bf[j][0], bf[j][1]);
        }
        __syncthreads();
    }

#pragma unroll
    for (int i = 0; i < 4; i++) {
        int r0 = bm + wm + 16 * i + g;
        int r1 = r0 + 8;
#pragma unroll
        for (int j = 0; j < 4; j++) {
            int c = bn + wn + 8 * j + 2 * t;
            float b0 = bias[c], b1 = bias[c + 1];
            float o00 = (acc[i][j][0] + b0) * scale;
            float o01 = (acc[i][j][1] + b1) * scale;
            float o10 = (acc[i][j][2] + b0) * scale;
            float o11 = (acc[i][j][3] + b1) * scale;
            if (cvt) {
                uint32_t* C = (uint32_t*)args.C[z];
                C[(size_t)r0 * EH_ + (c >> 1)] = pack_half2(o00, o01);
                C[(size_t)r1 * EH_ + (c >> 1)] = pack_half2(o10, o11);
            } else {
                float* C = (float*)args.C[z];
                *(float2*)&C[(size_t)r0 * EN_ + c] = make_float2(o00, o01);
                *(float2*)&C[(size_t)r1 * EN_ + c] = make_float2(o10, o11);
            }
        }
    }
}

// ---------------------------------------------------------------------------
extern "C" void kernel_launch(void* const* d_in, const int* in_sizes, int n_in,
                              void* d_out, int out_size)
{
    const float* query = (const float*)d_in[0];
    const float* key   = (const float*)d_in[1];
    const float* value = (const float*)d_in[2];
    const unsigned char* kpm       = (const unsigned char*)d_in[3];
    const unsigned char* attn_mask = (const unsigned char*)d_in[4];
    const float* Wq = (const float*)d_in[5];
    const float* bq = (const float*)d_in[6];
    const float* Wk = (const float*)d_in[7];
    const float* bk = (const float*)d_in[8];
    const float* Wv = (const float*)d_in[9];
    const float* bv = (const float*)d_in[10];
    const float* Wo = (const float*)d_in[11];
    const float* bo = (const float*)d_in[12];

    float* out = (float*)d_out;

    uint32_t *Qp, *Kp, *Vp, *Cm, *Eh;
    float *Ctx, *CtxP, *Part;
    cudaGetSymbolAddress((void**)&Qp,   g_Q);
    cudaGetSymbolAddress((void**)&Kp,   g_K);
    cudaGetSymbolAddress((void**)&Vp,   g_V);
    cudaGetSymbolAddress((void**)&Eh,   g_EH);
    cudaGetSymbolAddress((void**)&Ctx,  g_CTX);
    cudaGetSymbolAddress((void**)&CtxP, g_CTXP);
    cudaGetSymbolAddress((void**)&Part, g_PART);
    cudaGetSymbolAddress((void**)&Cm,   g_CMASK);

    int need_attn = ((size_t)out_size >= OUT0_ELEMS + P_ELEMS) ? 1 : 0;
    float* P = need_attn ? (out + OUT0_ELEMS) : out;

    dim3 blk(256);

    static int smem_set = 0;
    int smemA = 3 * 128 * 36 * 4;                       // 55296
    int smemB = (128 * 36 + 32 * 72) * 4 + 128 * 4;     // ~28.2 KB
    if (!smem_set) {
        cudaFuncSetAttribute(scores_exp_kernel, cudaFuncAttributeMaxDynamicSharedMemorySize, smemA);
        cudaFuncSetAttribute(pv_norm_kernel,    cudaFuncAttributeMaxDynamicSharedMemorySize, smemB);
        smem_set = 1;
    }

    pack_mask_kernel<<<(unsigned)((size_t)BN_ * TN_ * CM_WORDS / 256), blk>>>(attn_mask, kpm, Cm);

    const float Q_SCALE = 0.125f * 1.4426950408889634f;

    ProjArgs pa;
    pa.A[0] = query; pa.A[1] = key; pa.A[2] = value;
    pa.W[0] = Wq;    pa.W[1] = Wk;  pa.W[2] = Wv;
    pa.bias[0] = bq; pa.bias[1] = bk; pa.bias[2] = bv;
    pa.C[0] = Qp;    pa.C[1] = Kp;  pa.C[2] = Vp;
    pa.scale[0] = Q_SCALE; pa.scale[1] = 1.0f; pa.scale[2] = 1.0f;
    pa.cvt[0] = pa.cvt[1] = pa.cvt[2] = 1;
    dim3 gQKV(EN_ / 128, MPROJ / 128, 3);
    gemm_bias_kernel<<<gQKV, blk>>>(pa, EN_);

    dim3 gA(SN_ / (128 * NSB), TN_ / 128, BN_ * HN_);   // (4, 16, 32)
    scores_exp_kernel<<<gA, blk, smemA>>>(Qp, Kp, Cm, Eh, Part);

    dim3 gB(TN_ / 128, NSPLIT, BN_ * HN_);              // (16, 4, 32)
    pv_norm_kernel<<<gB, blk, smemB>>>(P, Eh, Vp, Part, CtxP, need_attn);

    combine_ctx_kernel<<<(unsigned)(CTX_ELEMS / 1024), blk>>>(CtxP, Ctx);

    ProjArgs po;
    po.A[0] = Ctx; po.W[0] = Wo; po.bias[0] = bo; po.C[0] = out; po.scale[0] = 1.0f;
    po.cvt[0] = 0;
    po.A[1] = po.A[2] = Ctx; po.W[1] = po.W[2] = Wo;
    po.bias[1] = po.bias[2] = bo; po.C[1] = po.C[2] = out;
    po.scale[1] = po.scale[2] = 1.0f; po.cvt[1] = po.cvt[2] = 0;
    dim3 gO(EN_ / 128, MPROJ / 128, 1);
    gemm_bias_kernel<<<gO, blk>>>(po, EN_);
}

// round 17
// speedup vs baseline: 1.0404x; 1.0404x over previous
#include <cuda_runtime.h>
#include <cuda_fp16.h>
#include <cstdint>
#include <cstddef>

#define BN_ 4
#define TN_ 2048
#define SN_ 2048
#define EN_ 512
#define HN_ 8
#define DH_ 64
#define MPROJ (BN_ * TN_)
#define NSB 4
#define NSBLK (SN_ / (128 * NSB))          // 4
#define NSPLIT 4
#define SCHUNK (SN_ / NSPLIT)              // 512
#define OUT0_ELEMS ((size_t)BN_ * TN_ * EN_)
#define P_ELEMS    ((size_t)BN_ * HN_ * TN_ * SN_)
#define CTX_ELEMS  ((size_t)MPROJ * EN_)
#define CM_WORDS   (SN_ / 32)
#define EH_ (EN_ / 2)
#define DHH_ (DH_ / 2)
#define SNH_ (SN_ / 2)

__device__ uint32_t g_Q[(size_t)MPROJ * EH_];
__device__ uint32_t g_K[(size_t)MPROJ * EH_];
__device__ uint32_t g_V[(size_t)MPROJ * EH_];
__device__ uint32_t g_EH[(size_t)BN_ * HN_ * TN_ * SNH_];
__device__ float g_CTX[CTX_ELEMS];
__device__ float g_CTXP[(size_t)NSPLIT * CTX_ELEMS];
__device__ float g_PART[(size_t)BN_ * HN_ * TN_ * NSBLK];
__device__ uint32_t g_CMASK[(size_t)BN_ * TN_ * CM_WORDS];

__device__ __forceinline__ uint32_t pack_half2(float lo, float hi) {
    __half2 h = __floats2half2_rn(lo, hi);
    return *(uint32_t*)&h;
}
__device__ __forceinline__ float2 unpack_half2(uint32_t u) {
    return __half22float2(*(__half2*)&u);
}
__device__ __forceinline__ uint32_t ex2_f16x2(uint32_t x) {
    uint32_t r;
    asm("ex2.approx.f16x2 %0, %1;" : "=r"(r) : "r"(x));
    return r;
}

__device__ __forceinline__ void mma_f16(
    float& d0, float& d1, float& d2, float& d3,
    uint32_t a0, uint32_t a1, uint32_t a2, uint32_t a3,
    uint32_t b0, uint32_t b1)
{
    asm volatile(
        "mma.sync.aligned.m16n8k16.row.col.f32.f16.f16.f32 "
        "{%0,%1,%2,%3}, {%4,%5,%6,%7}, {%8,%9}, {%0,%1,%2,%3};"
        : "+f"(d0), "+f"(d1), "+f"(d2), "+f"(d3)
        : "r"(a0), "r"(a1), "r"(a2), "r"(a3), "r"(b0), "r"(b1));
}

__device__ __forceinline__ void cp_async16(uint32_t smem_addr, const void* gptr) {
    asm volatile("cp.async.cg.shared.global [%0], [%1], 16;"
                 :: "r"(smem_addr), "l"(gptr));
}
#define CP_COMMIT() asm volatile("cp.async.commit_group;")
#define CP_WAIT0()  asm volatile("cp.async.wait_group 0;")

// ---------------------------------------------------------------------------
__global__ __launch_bounds__(256) void pack_mask_kernel(
    const unsigned char* __restrict__ attn_mask,
    const unsigned char* __restrict__ kpm,
    uint32_t* __restrict__ cmask)
{
    size_t idx = (size_t)blockIdx.x * 256 + threadIdx.x;
    int w = (int)(idx & (CM_WORDS - 1));
    size_t bt = idx >> 6;
    int t = (int)(bt & (TN_ - 1));
    int b = (int)(bt >> 11);

    const uint32_t* am = (const uint32_t*)&attn_mask[(size_t)t * SN_ + w * 32];
    const uint32_t* kp = (const uint32_t*)&kpm[(size_t)b * SN_ + w * 32];
    uint32_t bits = 0;
#pragma unroll
    for (int j = 0; j < 8; j++) {
        uint32_t u = am[j] | kp[j];
#pragma unroll
        for (int k = 0; k < 4; k++)
            if ((u >> (8 * k)) & 255u) bits |= 1u << (4 * j + k);
    }
    cmask[idx] = bits;
}

// ---------------------------------------------------------------------------
// Kernel A: fp16 scores in log2 domain, persistent over 4 s-tiles,
// cp.async double-buffered K. Mask words hoisted BEFORE the mma loop so
// their DRAM latency hides under tensor work; epilogue: ex2.f16x2 + E write.
// ---------------------------------------------------------------------------
__global__ __launch_bounds__(256, 2) void scores_exp_kernel(
    const uint32_t* __restrict__ Q, const uint32_t* __restrict__ Kp,
    const uint32_t* __restrict__ cmask,
    uint32_t* __restrict__ EH, float* __restrict__ part)
{
    extern __shared__ uint32_t smem_u[];
    uint32_t* Qs  = smem_u;
    uint32_t* Ks0 = smem_u + 128 * 36;
    uint32_t* Ks1 = smem_u + 2 * 128 * 36;
    __shared__ float ssum[4][128];

    int bh = blockIdx.z;
    int b = bh >> 3;
    int h = bh & 7;
    int t0 = blockIdx.y * 128;
    int sBase = blockIdx.x * (128 * NSB);
    int tid = threadIdx.x;
    int warp = tid >> 5, lane = tid & 31;
    int g = lane >> 2, t = lane & 3;
    int wm = (warp >> 2) * 64;
    int wn = (warp & 3) * 32;

    const uint32_t* Qb = Q + (size_t)b * TN_ * EH_ + (size_t)h * DHH_;
    const uint32_t* Kb = Kp + (size_t)b * SN_ * EH_ + (size_t)h * DHH_;

    uint32_t qs_a  = (uint32_t)__cvta_generic_to_shared(Qs);
    uint32_t ks_a[2] = { (uint32_t)__cvta_generic_to_shared(Ks0),
                         (uint32_t)__cvta_generic_to_shared(Ks1) };

#pragma unroll
    for (int i = 0; i < 4; i++) {
        int f = tid + i * 256;
        int r = f >> 3;
        int ch = (f & 7) * 4;
        cp_async16(qs_a + (r * 36 + ch) * 4, Qb + (size_t)(t0 + r) * EH_ + ch);
    }
#pragma unroll
    for (int i = 0; i < 4; i++) {
        int f = tid + i * 256;
        int r = f >> 3;
        int ch = (f & 7) * 4;
        cp_async16(ks_a[0] + (r * 36 + ch) * 4, Kb + (size_t)(sBase + r) * EH_ + ch);
    }
    CP_COMMIT();

    uint32_t* Eb = EH + (size_t)bh * TN_ * SNH_;
    const uint32_t* cm = cmask + ((size_t)b * TN_ << 6);
    float partial[4][2] = {};

    CP_WAIT0();
    __syncthreads();

    for (int si = 0; si < NSB; si++) {
        uint32_t* Kcur = (si & 1) ? Ks1 : Ks0;

        if (si + 1 < NSB) {
            int s0n = sBase + (si + 1) * 128;
            uint32_t dst = ks_a[(si + 1) & 1];
#pragma unroll
            for (int i = 0; i < 4; i++) {
                int f = tid + i * 256;
                int r = f >> 3;
                int ch = (f & 7) * 4;
                cp_async16(dst + (r * 36 + ch) * 4, Kb + (size_t)(s0n + r) * EH_ + ch);
            }
            CP_COMMIT();
        }

        int s0 = sBase + si * 128;

        // Hoisted mask loads: issue before mma so latency hides under HMMA.
        int w = (s0 + wn) >> 5;
        uint32_t mw[4][2];
#pragma unroll
        for (int i = 0; i < 4; i++) {
            int tg0 = t0 + wm + 16 * i + g;
            mw[i][0] = __ldg(&cm[((size_t)tg0 << 6) + w]);
            mw[i][1] = __ldg(&cm[((size_t)(tg0 + 8) << 6) + w]);
        }

        float acc[4][4][4] = {};
#pragma unroll
        for (int kk2 = 0; kk2 < 32; kk2 += 8) {
            uint32_t a[4][4];
#pragma unroll
            for (int i = 0; i < 4; i++) {
                int base = (wm + 16 * i + g) * 36 + kk2 + t;
                a[i][0] = Qs[base];
                a[i][1] = Qs[base + 8 * 36];
                a[i][2] = Qs[base + 4];
                a[i][3] = Qs[base + 8 * 36 + 4];
            }
            uint32_t bf[4][2];
#pragma unroll
            for (int j = 0; j < 4; j++) {
                int base = (wn + 8 * j + g) * 36 + kk2 + t;
                bf[j][0] = Kcur[base];
                bf[j][1] = Kcur[base + 4];
            }
#pragma unroll
            for (int i = 0; i < 4; i++)
#pragma unroll
                for (int j = 0; j < 4; j++)
                    mma_f16(acc[i][j][0], acc[i][j][1], acc[i][j][2], acc[i][j][3],
                            a[i][0], a[i][1], a[i][2], a[i][3], bf[j][0], bf[j][1]);
        }

#pragma unroll
        for (int i = 0; i < 4; i++) {
            int tg0 = t0 + wm + 16 * i + g;
            int tg1 = tg0 + 8;
            uint32_t w0 = mw[i][0];
            uint32_t w1 = mw[i][1];
#pragma unroll
            for (int j = 0; j < 4; j++) {
                int bit = 8 * j + 2 * t;
                int sh = (s0 + wn + bit) >> 1;
                float m00 = ((w0 >> bit) & 1u) ? -100.f : acc[i][j][0];
                float m01 = ((w0 >> bit) & 2u) ? -100.f : acc[i][j][1];
                float m10 = ((w1 >> bit) & 1u) ? -100.f : acc[i][j][2];
                float m11 = ((w1 >> bit) & 2u) ? -100.f : acc[i][j][3];
                uint32_t p0 = ex2_f16x2(pack_half2(m00, m01));
                uint32_t p1 = ex2_f16x2(pack_half2(m10, m11));
                __stcs(&Eb[(size_t)tg0 * SNH_ + sh], p0);
                __stcs(&Eb[(size_t)tg1 * SNH_ + sh], p1);
                float2 f0 = unpack_half2(p0);
                float2 f1 = unpack_half2(p1);
                partial[i][0] += f0.x + f0.y;
                partial[i][1] += f1.x + f1.y;
            }
        }

        if (si + 1 < NSB) {
            CP_WAIT0();
            __syncthreads();
        }
    }

#pragma unroll
    for (int i = 0; i < 4; i++)
#pragma unroll
        for (int hh = 0; hh < 2; hh++) {
            float v = partial[i][hh];
            v += __shfl_xor_sync(0xFFFFFFFFu, v, 1);
            v += __shfl_xor_sync(0xFFFFFFFFu, v, 2);
            partial[i][hh] = v;
        }
    if (t == 0) {
#pragma unroll
        for (int i = 0; i < 4; i++)
#pragma unroll
            for (int hh = 0; hh < 2; hh++)
                ssum[warp & 3][wm + 16 * i + 8 * hh + g] = partial[i][hh];
    }
    __syncthreads();
    if (tid < 128) {
        float l = ssum[0][tid] + ssum[1][tid] + ssum[2][tid] + ssum[3][tid];
        part[((size_t)bh * TN_ + t0 + tid) * NSBLK + blockIdx.x] = l;
    }
}

// ---------------------------------------------------------------------------
// Kernel B (exact R14): split-S PV (fp16 mma), packed-half2 E, fused invl,
// register prefetch, single smem buffer.
// ---------------------------------------------------------------------------
__global__ __launch_bounds__(256) void pv_norm_kernel(
    float* __restrict__ P, const uint32_t* __restrict__ EH,
    const uint32_t* __restrict__ V,
    const float* __restrict__ part, float* __restrict__ ctxp, int writeP)
{
    extern __shared__ uint32_t smem_b[];
    uint32_t* Ps = smem_b;                 // 128 * 36
    uint32_t* Vs = smem_b + 128 * 36;      // 32 * 72
    float* sinv = (float*)(smem_b + 128 * 36 + 32 * 72);

    int bh = blockIdx.z;
    int b = bh >> 3;
    int h = bh & 7;
    int sc = blockIdx.y;
    int t0 = blockIdx.x * 128;
    int tid = threadIdx.x;
    int warp = tid >> 5, lane = tid & 31;
    int g = lane >> 2, t = lane & 3;
    int wm = (warp >> 1) * 32;
    int wn = (warp & 1) * 32;

    float* Pb = P + ((size_t)bh * TN_ + t0) * SN_;
    const uint32_t* Eb = EH + ((size_t)bh * TN_ + t0) * SNH_;
    const uint32_t* Vb = V + (size_t)b * SN_ * EH_ + (size_t)h * DHH_;

    if (tid < 128) {
        float4 v = *(const float4*)&part[((size_t)bh * TN_ + t0 + tid) * NSBLK];
        sinv[tid] = 1.0f / ((v.x + v.y) + (v.z + v.w));
    }

    uint4 eReg[4];
    uint4 vReg[2];

    {
        int k0h = sc * (SCHUNK / 2);
#pragma unroll
        for (int i = 0; i < 4; i++) {
            int f = tid + i * 256;
            int r = f >> 3, c = (f & 7) * 4;
            eReg[i] = __ldcs((const uint4*)&Eb[(size_t)r * SNH_ + k0h + c]);
        }
#pragma unroll
        for (int i = 0; i < 2; i++) {
            int f = tid + i * 256;
            int sp = f >> 4, cg = f & 15;
            const uint32_t* r0 = Vb + (size_t)(sc * SCHUNK + 2 * sp) * EH_ + 2 * cg;
            uint2 v0 = *(const uint2*)r0;
            uint2 v1 = *(const uint2*)(r0 + EH_);
            vReg[i] = make_uint4(v0.x, v0.y, v1.x, v1.y);
        }
    }
    __syncthreads();

    float acc[2][4][4] = {};
    const int NIT = SCHUNK / 64;   // 8

    for (int it = 0; it < NIT; it++) {
        int k0 = sc * SCHUNK + it * 64;
#pragma unroll
        for (int i = 0; i < 4; i++) {
            int f = tid + i * 256;
            int r = f >> 3, c = (f & 7) * 4;
            uint4 e = eReg[i];
            *(uint4*)&Ps[r * 36 + c] = e;
            if (writeP) {
                float iv = sinv[r];
                float2 f0 = unpack_half2(e.x);
                float2 f1 = unpack_half2(e.y);
                float2 f2 = unpack_half2(e.z);
                float2 f3 = unpack_half2(e.w);
                float4 o0 = make_float4(f0.x * iv, f0.y * iv, f1.x * iv, f1.y * iv);
                float4 o1 = make_float4(f2.x * iv, f2.y * iv, f3.x * iv, f3.y * iv);
                __stcs((float4*)&Pb[(size_t)r * SN_ + k0 + 2 * c], o0);
                __stcs((float4*)&Pb[(size_t)r * SN_ + k0 + 2 * c + 4], o1);
            }
        }
#pragma unroll
        for (int i = 0; i < 2; i++) {
            int f = tid + i * 256;
            int sp = f >> 4, cg = f & 15;
            __half2 a0 = *(__half2*)&vReg[i].x;
            __half2 a1 = *(__half2*)&vReg[i].y;
            __half2 b0 = *(__half2*)&vReg[i].z;
            __half2 b1 = *(__half2*)&vReg[i].w;
            __half2 o0 = __lows2half2(a0, b0);
            __half2 o1 = __highs2half2(a0, b0);
            __half2 o2 = __lows2half2(a1, b1);
            __half2 o3 = __highs2half2(a1, b1);
            uint32_t* dst = &Vs[sp * 72 + 4 * cg];
            dst[0] = *(uint32_t*)&o0; dst[1] = *(uint32_t*)&o1;
            dst[2] = *(uint32_t*)&o2; dst[3] = *(uint32_t*)&o3;
        }
        __syncthreads();

        if (it + 1 < NIT) {
            int k1 = k0 + 64;
            int k1h = k1 >> 1;
#pragma unroll
            for (int i = 0; i < 4; i++) {
                int f = tid + i * 256;
                int r = f >> 3, c = (f & 7) * 4;
                eReg[i] = __ldcs((const uint4*)&Eb[(size_t)r * SNH_ + k1h + c]);
            }
#pragma unroll
            for (int i = 0; i < 2; i++) {
                int f = tid + i * 256;
                int sp = f >> 4, cg = f & 15;
                const uint32_t* r0 = Vb + (size_t)(k1 + 2 * sp) * EH_ + 2 * cg;
                uint2 v0 = *(const uint2*)r0;
                uint2 v1 = *(const uint2*)(r0 + EH_);
                vReg[i] = make_uint4(v0.x, v0.y, v1.x, v1.y);
            }
        }

#pragma unroll
        for (int kk2 = 0; kk2 < 32; kk2 += 8) {
            uint32_t a[2][4];
#pragma unroll
            for (int i = 0; i < 2; i++) {
                int base = (wm + 16 * i + g) * 36 + kk2 + t;
                a[i][0] = Ps[base];
                a[i][1] = Ps[base + 8 * 36];
                a[i][2] = Ps[base + 4];
                a[i][3] = Ps[base + 8 * 36 + 4];
            }
            uint32_t bf[4][2];
#pragma unroll
            for (int j = 0; j < 4; j++) {
                int col = wn + 8 * j + g;
                bf[j][0] = Vs[(kk2 + t) * 72 + col];
                bf[j][1] = Vs[(kk2 + t + 4) * 72 + col];
            }
#pragma unroll
            for (int i = 0; i < 2; i++)
#pragma unroll
                for (int j = 0; j < 4; j++)
                    mma_f16(acc[i][j][0], acc[i][j][1], acc[i][j][2], acc[i][j][3],
                            a[i][0], a[i][1], a[i][2], a[i][3], bf[j][0], bf[j][1]);
        }
        __syncthreads();
    }

    float* Cp = ctxp + (size_t)sc * CTX_ELEMS + (size_t)b * TN_ * EN_ + (size_t)h * DH_;
#pragma unroll
    for (int i = 0; i < 2; i++) {
        int rl0 = wm + 16 * i + g;
        int rl1 = rl0 + 8;
        float iv0 = sinv[rl0];
        float iv1 = sinv[rl1];
        int r0 = t0 + rl0, r1 = t0 + rl1;
#pragma unroll
        for (int j = 0; j < 4; j++) {
            int d = wn + 8 * j + 2 * t;
            *(float2*)&Cp[(size_t)r0 * EN_ + d] =
                make_float2(acc[i][j][0] * iv0, acc[i][j][1] * iv0);
            *(float2*)&Cp[(size_t)r1 * EN_ + d] =
                make_float2(acc[i][j][2] * iv1, acc[i][j][3] * iv1);
        }
    }
}

// ---------------------------------------------------------------------------
__global__ __launch_bounds__(256) void combine_ctx_kernel(
    const float* __restrict__ ctxp, float* __restrict__ ctx)
{
    size_t i = ((size_t)blockIdx.x * 256 + threadIdx.x) * 4;
    float4 a = __ldcs((const float4*)&ctxp[0 * CTX_ELEMS + i]);
    float4 b = __ldcs((const float4*)&ctxp[1 * CTX_ELEMS + i]);
    float4 c = __ldcs((const float4*)&ctxp[2 * CTX_ELEMS + i]);
    float4 d = __ldcs((const float4*)&ctxp[3 * CTX_ELEMS + i]);
    float4 o;
    o.x = (a.x + b.x) + (c.x + d.x);
    o.y = (a.y + b.y) + (c.y + d.y);
    o.z = (a.z + b.z) + (c.z + d.z);
    o.w = (a.w + b.w) + (c.w + d.w);
    *(float4*)&ctx[i] = o;
}

// ---------------------------------------------------------------------------
// Projection GEMM, fp16 mma (fp32 accum), register prefetch, BK=32.
// ---------------------------------------------------------------------------
struct ProjArgs {
    const float* A[3];
    const float* W[3];
    const float* bias[3];
    void* C[3];
    float scale[3];
    int cvt[3];
};

__global__ __launch_bounds__(256) void gemm_bias_kernel(
    ProjArgs args, int K)
{
    __shared__ uint32_t As[128 * 20];
    __shared__ uint32_t Ws[16 * 136];

    int z = blockIdx.z;
    const float* __restrict__ A = args.A[z];
    const float* __restrict__ W = args.W[z];
    const float* __restrict__ bias = args.bias[z];
    float scale = args.scale[z];
    int cvt = args.cvt[z];
    const int N = EN_;

    int tid = threadIdx.x;
    int warp = tid >> 5, lane = tid & 31;
    int g = lane >> 2, t = lane & 3;
    int wm = (warp >> 2) * 64;
    int wn = (warp & 3) * 32;
    int bm = blockIdx.y * 128, bn = blockIdx.x * 128;

    float acc[4][4][4] = {};

    float4 aReg[4];
    float4 wReg[2][2];
#pragma unroll
    for (int i = 0; i < 4; i++) {
        int f = tid + i * 256;
        int r = f >> 3, c = (f & 7) * 4;
        aReg[i] = *(const float4*)&A[(size_t)(bm + r) * K + c];
    }
#pragma unroll
    for (int i = 0; i < 2; i++) {
        int f = tid + i * 256;
        int kp = f >> 5, ng = (f & 31) * 4;
        wReg[i][0] = *(const float4*)&W[(size_t)(2 * kp) * N + bn + ng];
        wReg[i][1] = *(const float4*)&W[(size_t)(2 * kp + 1) * N + bn + ng];
    }

    for (int k0 = 0; k0 < K; k0 += 32) {
#pragma unroll
        for (int i = 0; i < 4; i++) {
            int f = tid + i * 256;
            int r = f >> 3, c = (f & 7) * 4;
            float4 v = aReg[i];
            As[r * 20 + (c >> 1)]     = pack_half2(v.x, v.y);
            As[r * 20 + (c >> 1) + 1] = pack_half2(v.z, v.w);
        }
#pragma unroll
        for (int i = 0; i < 2; i++) {
            int f = tid + i * 256;
            int kp = f >> 5, ng = (f & 31) * 4;
            float4 lo = wReg[i][0], hi = wReg[i][1];
            uint32_t* dst = &Ws[kp * 136 + ng];
            dst[0] = pack_half2(lo.x, hi.x);
            dst[1] = pack_half2(lo.y, hi.y);
            dst[2] = pack_half2(lo.z, hi.z);
            dst[3] = pack_half2(lo.w, hi.w);
        }
        __syncthreads();

        if (k0 + 32 < K) {
            int k1 = k0 + 32;
#pragma unroll
            for (int i = 0; i < 4; i++) {
                int f = tid + i * 256;
                int r = f >> 3, c = (f & 7) * 4;
                aReg[i] = *(const float4*)&A[(size_t)(bm + r) * K + k1 + c];
            }
#pragma unroll
            for (int i = 0; i < 2; i++) {
                int f = tid + i * 256;
                int kp = f >> 5, ng = (f & 31) * 4;
                wReg[i][0] = *(const float4*)&W[(size_t)(k1 + 2 * kp) * N + bn + ng];
                wReg[i][1] = *(const float4*)&W[(size_t)(k1 + 2 * kp + 1) * N + bn + ng];
            }
        }

#pragma unroll
        for (int kk2 = 0; kk2 < 16; kk2 += 8) {
            uint32_t a[4][4];
#pragma unroll
            for (int i = 0; i < 4; i++) {
                int base = (wm + 16 * i + g) * 20 + kk2 + t;
                a[i][0] = As[base];
                a[i][1] = As[base + 8 * 20];
                a[i][2] = As[base + 4];
                a[i][3] = As[base + 8 * 20 + 4];
            }
            uint32_t bf[4][2];
#pragma unroll
            for (int j = 0; j < 4; j++) {
                int col = wn + 8 * j + g;
                bf[j][0] = Ws[(kk2 + t) * 136 + col];
                bf[j][1] = Ws[(kk2 + t + 4) * 136 + col];
            }
#pragma unroll
            for (int i = 0; i < 4; i++)
#pragma unroll
                for (int j = 0; j < 4; j++)
                    mma_f16(acc[i][j][0], acc[i][j][1], acc[i][j][2], acc[i][j][3],
                            a[i][0], a[i][1], a[i][2], a[i][3], bf[j][0], bf[j][1]);
        }
        __syncthreads();
    }

#pragma unroll
    for (int i = 0; i < 4; i++) {
        int r0 = bm + wm + 16 * i + g;
        int r1 = r0 + 8;
#pragma unroll
        for (int j = 0; j < 4; j++) {
            int c = bn + wn + 8 * j + 2 * t;
            float b0 = bias[c], b1 = bias[c + 1];
            float o00 = (acc[i][j][0] + b0) * scale;
            float o01 = (acc[i][j][1] + b1) * scale;
            float o10 = (acc[i][j][2] + b0) * scale;
            float o11 = (acc[i][j][3] + b1) * scale;
            if (cvt) {
                uint32_t* C = (uint32_t*)args.C[z];
                C[(size_t)r0 * EH_ + (c >> 1)] = pack_half2(o00, o01);
                C[(size_t)r1 * EH_ + (c >> 1)] = pack_half2(o10, o11);
            } else {
                float* C = (float*)args.C[z];
                *(float2*)&C[(size_t)r0 * EN_ + c] = make_float2(o00, o01);
                *(float2*)&C[(size_t)r1 * EN_ + c] = make_float2(o10, o11);
            }
        }
    }
}

// ---------------------------------------------------------------------------
extern "C" void kernel_launch(void* const* d_in, const int* in_sizes, int n_in,
                              void* d_out, int out_size)
{
    const float* query = (const float*)d_in[0];
    const float* key   = (const float*)d_in[1];
    const float* value = (const float*)d_in[2];
    const unsigned char* kpm       = (const unsigned char*)d_in[3];
    const unsigned char* attn_mask = (const unsigned char*)d_in[4];
    const float* Wq = (const float*)d_in[5];
    const float* bq = (const float*)d_in[6];
    const float* Wk = (const float*)d_in[7];
    const float* bk = (const float*)d_in[8];
    const float* Wv = (const float*)d_in[9];
    const float* bv = (const float*)d_in[10];
    const float* Wo = (const float*)d_in[11];
    const float* bo = (const float*)d_in[12];

    float* out = (float*)d_out;

    uint32_t *Qp, *Kp, *Vp, *Cm, *Eh;
    float *Ctx, *CtxP, *Part;
    cudaGetSymbolAddress((void**)&Qp,   g_Q);
    cudaGetSymbolAddress((void**)&Kp,   g_K);
    cudaGetSymbolAddress((void**)&Vp,   g_V);
    cudaGetSymbolAddress((void**)&Eh,   g_EH);
    cudaGetSymbolAddress((void**)&Ctx,  g_CTX);
    cudaGetSymbolAddress((void**)&CtxP, g_CTXP);
    cudaGetSymbolAddress((void**)&Part, g_PART);
    cudaGetSymbolAddress((void**)&Cm,   g_CMASK);

    int need_attn = ((size_t)out_size >= OUT0_ELEMS + P_ELEMS) ? 1 : 0;
    float* P = need_attn ? (out + OUT0_ELEMS) : out;

    dim3 blk(256);

    static int smem_set = 0;
    int smemA = 3 * 128 * 36 * 4;                       // 55296
    int smemB = (128 * 36 + 32 * 72) * 4 + 128 * 4;     // ~28.2 KB
    if (!smem_set) {
        cudaFuncSetAttribute(scores_exp_kernel, cudaFuncAttributeMaxDynamicSharedMemorySize, smemA);
        cudaFuncSetAttribute(pv_norm_kernel,    cudaFuncAttributeMaxDynamicSharedMemorySize, smemB);
        smem_set = 1;
    }

    pack_mask_kernel<<<(unsigned)((size_t)BN_ * TN_ * CM_WORDS / 256), blk>>>(attn_mask, kpm, Cm);

    const float Q_SCALE = 0.125f * 1.4426950408889634f;

    ProjArgs pa;
    pa.A[0] = query; pa.A[1] = key; pa.A[2] = value;
    pa.W[0] = Wq;    pa.W[1] = Wk;  pa.W[2] = Wv;
    pa.bias[0] = bq; pa.bias[1] = bk; pa.bias[2] = bv;
    pa.C[0] = Qp;    pa.C[1] = Kp;  pa.C[2] = Vp;
    pa.scale[0] = Q_SCALE; pa.scale[1] = 1.0f; pa.scale[2] = 1.0f;
    pa.cvt[0] = pa.cvt[1] = pa.cvt[2] = 1;
    dim3 gQKV(EN_ / 128, MPROJ / 128, 3);
    gemm_bias_kernel<<<gQKV, blk>>>(pa, EN_);

    dim3 gA(SN_ / (128 * NSB), TN_ / 128, BN_ * HN_);   // (4, 16, 32)
    scores_exp_kernel<<<gA, blk, smemA>>>(Qp, Kp, Cm, Eh, Part);

    dim3 gB(TN_ / 128, NSPLIT, BN_ * HN_);              // (16, 4, 32)
    pv_norm_kernel<<<gB, blk, smemB>>>(P, Eh, Vp, Part, CtxP, need_attn);

    combine_ctx_kernel<<<(unsigned)(CTX_ELEMS / 1024), blk>>>(CtxP, Ctx);

    ProjArgs po;
    po.A[0] = Ctx; po.W[0] = Wo; po.bias[0] = bo; po.C[0] = out; po.scale[0] = 1.0f;
    po.cvt[0] = 0;
    po.A[1] = po.A[2] = Ctx; po.W[1] = po.W[2] = Wo;
    po.bias[1] = po.bias[2] = bo; po.C[1] = po.C[2] = out;
    po.scale[1] = po.scale[2] = 1.0f; po.cvt[1] = po.cvt[2] = 0;
    dim3 gO(EN_ / 128, MPROJ / 128, 1);
    gemm_bias_kernel<<<gO, blk>>>(po, EN_);
}